// round 3
// baseline (speedup 1.0000x reference)
#include <cuda_runtime.h>
#include <cstdint>

#define B_ 4
#define H_ 16
#define T_ 4096
#define D_ 64
#define U_ 134
#define NH (B_*H_)        // 64 heads
#define NSPLIT 4
#define KPS (T_/NSPLIT)   // 1024 keys per split
#define KT 64             // key tile
#define NTILES (KPS/KT)   // 16
#define MROWS 144         // 9 warps * 16 rows (134 padded)
#define NWARPS 9
#define SSTRIDE 68        // smem row stride in 32-bit words (bank-conflict pad)

// ---------------- device scratch (no allocations allowed) ----------------
__device__ __align__(16) float g_score[NH*T_];
__device__ int   g_topidx[NH*U_];
__device__ __align__(16) float g_vmean[NH*D_];
__device__ __align__(16) float g_m[NSPLIT*NH*U_];
__device__ __align__(16) float g_l[NSPLIT*NH*U_];
__device__ __align__(16) float g_opart[(size_t)NSPLIT*NH*U_*D_];

// ---------------- helpers ----------------
__device__ __forceinline__ unsigned f2tf(float x){
    unsigned r; asm("cvt.rna.tf32.f32 %0, %1;" : "=r"(r) : "f"(x)); return r;
}
__device__ __forceinline__ float ex2f(float x){
    float y; asm("ex2.approx.ftz.f32 %0, %1;" : "=f"(y) : "f"(x)); return y;
}
__device__ __forceinline__ void mma8(float& d0,float& d1,float& d2,float& d3,
        unsigned a0,unsigned a1,unsigned a2,unsigned a3,
        unsigned b0,unsigned b1){
    asm volatile("mma.sync.aligned.m16n8k8.row.col.f32.tf32.tf32.f32 "
        "{%0,%1,%2,%3}, {%4,%5,%6,%7}, {%8,%9}, {%0,%1,%2,%3};"
        : "+f"(d0),"+f"(d1),"+f"(d2),"+f"(d3)
        : "r"(a0),"r"(a1),"r"(a2),"r"(a3),"r"(b0),"r"(b1));
}
// column permutation within each 8-group so that (t, t+4) are adjacent -> LDS.64 pairs
__device__ __forceinline__ int permd(int d){
    return (d & ~7) | ((d & 3) << 1) | ((d >> 2) & 1);
}

// ---------------- 1. q_score = sum(Q*Q, -1) ----------------
__global__ void qscore_kernel(const float* __restrict__ Q){
    int row  = blockIdx.x*8 + (threadIdx.x>>5);
    int lane = threadIdx.x & 31;
    const float* q = Q + (size_t)row*D_;
    float a = q[lane], b = q[lane+32];
    float s = a*a + b*b;
    #pragma unroll
    for (int o=16;o;o>>=1) s += __shfl_xor_sync(~0u, s, o);
    if (!lane) g_score[row] = s;
}

// ---------------- 2. per-head top-134 (radix select on float bits; scores >= 0) ----------------
__global__ void topk_kernel(){
    int hd = blockIdx.x;
    const float* sc = g_score + hd*T_;
    __shared__ int hist[256];
    __shared__ unsigned s_prefix;
    __shared__ int s_rem, s_gt, s_eq, s_need;
    int tid = threadIdx.x;
    if (tid==0){ s_prefix=0u; s_rem=U_; }
    __syncthreads();
    for (int shift=24; shift>=0; shift-=8){
        hist[tid]=0;
        __syncthreads();
        unsigned pfx = s_prefix;
        for (int i=tid;i<T_;i+=256){
            unsigned b = __float_as_uint(sc[i]);
            bool match = (shift==24) || ((b>>(shift+8))==(pfx>>(shift+8)));
            if (match) atomicAdd(&hist[(b>>shift)&255],1);
        }
        __syncthreads();
        if (tid==0){
            int rem = s_rem, cum=0, d=255;
            for (; d>=0; --d){ cum += hist[d]; if (cum>=rem) break; }
            s_rem = rem - (cum - hist[d]);
            s_prefix = pfx | ((unsigned)d<<shift);
        }
        __syncthreads();
    }
    if (tid==0){ s_gt=0; s_eq=0; s_need=s_rem; }
    __syncthreads();
    unsigned Tb = s_prefix;
    int need = s_need;
    int base_eq = U_ - need;
    for (int i=tid;i<T_;i+=256){
        unsigned b = __float_as_uint(sc[i]);
        if (b > Tb){
            int p = atomicAdd(&s_gt,1);
            g_topidx[hd*U_+p] = i;
        } else if (b == Tb){
            int p = atomicAdd(&s_eq,1);
            if (p < need) g_topidx[hd*U_+base_eq+p] = i;
        }
    }
}

// ---------------- 3a. Vmean ----------------
__global__ void vmean_kernel(const float* __restrict__ V){
    int hd = blockIdx.x;
    int d  = threadIdx.x & 63, rg = threadIdx.x >> 6;   // block 1024 -> rg 0..15
    const float* v = V + (size_t)hd*T_*D_ + d;
    float acc=0.f;
    #pragma unroll 4
    for (int r=rg; r<T_; r+=16) acc += v[(size_t)r*D_];
    __shared__ float sm[1024];
    sm[threadIdx.x]=acc;
    __syncthreads();
    if (threadIdx.x < 64){
        float s=0.f;
        #pragma unroll
        for (int j=0;j<16;j++) s += sm[j*64 + d];
        g_vmean[hd*D_+d] = s * (1.0f/T_);
    }
}

// ---------------- 3b. broadcast Vmean to every output row ----------------
__global__ void bcast_kernel(float4* __restrict__ out){
    const float4* vm = (const float4*)g_vmean;
    unsigned idx = blockIdx.x*blockDim.x + threadIdx.x;
    #pragma unroll
    for (int it=0; it<2; ++it){
        unsigned j = idx + it*2097152u;
        unsigned head = j >> 16;     // 4096*16 float4 per head
        unsigned dq   = j & 15;
        out[j] = vm[head*16 + dq];
    }
}

// ---------------- 4. split-KV flash attention on selected queries (tf32 mma) ----------------
__global__ void __launch_bounds__(NWARPS*32) attn_kernel(
        const float* __restrict__ Q, const float* __restrict__ K,
        const float* __restrict__ V){
    extern __shared__ unsigned smem[];
    unsigned* KS = smem;                  // KT x SSTRIDE (tf32 bits, d-permuted)
    unsigned* VS = smem + KT*SSTRIDE;     // KT x SSTRIDE (tf32 bits)
    unsigned* PS = VS   + KT*SSTRIDE;     // MROWS x SSTRIDE (tf32 bits; also Q staging)

    int sp = blockIdx.x, hd = blockIdx.y;
    int tid = threadIdx.x;
    int wid = tid>>5, lane = tid&31;
    int g = lane>>2, t = lane&3;
    int wm = wid*16;
    const float SL = 0.18033688011112042f;  // (1/sqrt(64)) * log2(e)

    // --- stage selected Q rows (padded to 144) into PS ---
    const int* tix = g_topidx + hd*U_;
    {
        size_t qbase = (size_t)hd*T_*D_;
        for (int i=tid; i<MROWS*D_; i+=NWARPS*32){
            int r = i>>6, d = i&63;
            float v = 0.f;
            if (r < U_) v = Q[qbase + (size_t)tix[r]*D_ + d];
            PS[r*SSTRIDE + permd(d)] = f2tf(v);
        }
    }
    __syncthreads();

    // --- Q A-fragments into registers (persist through key loop) ---
    unsigned qf[8][4];
    #pragma unroll
    for (int k=0;k<8;k++){
        uint2 lo = *(const uint2*)&PS[(wm+g  )*SSTRIDE + 8*k + 2*t];
        uint2 hi = *(const uint2*)&PS[(wm+g+8)*SSTRIDE + 8*k + 2*t];
        qf[k][0]=lo.x; qf[k][1]=hi.x; qf[k][2]=lo.y; qf[k][3]=hi.y;
    }

    float m1=-1e30f, m2=-1e30f, l1=0.f, l2=0.f;
    float oacc[8][4];
    #pragma unroll
    for (int dtl=0;dtl<8;dtl++){ oacc[dtl][0]=0.f; oacc[dtl][1]=0.f; oacc[dtl][2]=0.f; oacc[dtl][3]=0.f; }

    // P-store permuted column offsets (within an 8-group)
    int pc0 = (((2*t  )&3)<<1) | (((2*t  )>>2)&1);
    int pc1 = (((2*t+1)&3)<<1) | (((2*t+1)>>2)&1);

    size_t kvbase = ((size_t)hd*T_ + (size_t)sp*KPS)*D_;
    for (int ktile=0; ktile<NTILES; ++ktile){
        // --- stage K, V tiles ---
        const float* Kg = K + kvbase + (size_t)ktile*KT*D_;
        const float* Vg = V + kvbase + (size_t)ktile*KT*D_;
        for (int i=tid; i<KT*D_; i+=NWARPS*32){
            int r = i>>6, d = i&63;
            KS[r*SSTRIDE + permd(d)] = f2tf(Kg[i]);
            VS[r*SSTRIDE + d]        = f2tf(Vg[i]);
        }
        __syncthreads();

        // --- S = Q K^T (16 x 64 per warp) ---
        float sacc[8][4];
        #pragma unroll
        for (int nt=0;nt<8;nt++){ sacc[nt][0]=0.f; sacc[nt][1]=0.f; sacc[nt][2]=0.f; sacc[nt][3]=0.f; }
        #pragma unroll
        for (int k=0;k<8;k++){
            #pragma unroll
            for (int nt=0;nt<8;nt++){
                uint2 b = *(const uint2*)&KS[(8*nt+g)*SSTRIDE + 8*k + 2*t];
                mma8(sacc[nt][0],sacc[nt][1],sacc[nt][2],sacc[nt][3],
                     qf[k][0],qf[k][1],qf[k][2],qf[k][3], b.x, b.y);
            }
        }

        // --- online softmax (base 2, scale folded) ---
        float tm1=-1e30f, tm2=-1e30f;
        #pragma unroll
        for (int nt=0;nt<8;nt++){
            tm1 = fmaxf(tm1, fmaxf(sacc[nt][0], sacc[nt][1]));
            tm2 = fmaxf(tm2, fmaxf(sacc[nt][2], sacc[nt][3]));
        }
        tm1 *= SL; tm2 *= SL;
        tm1 = fmaxf(tm1, __shfl_xor_sync(~0u,tm1,1)); tm1 = fmaxf(tm1, __shfl_xor_sync(~0u,tm1,2));
        tm2 = fmaxf(tm2, __shfl_xor_sync(~0u,tm2,1)); tm2 = fmaxf(tm2, __shfl_xor_sync(~0u,tm2,2));
        float m1n = fmaxf(m1,tm1), m2n = fmaxf(m2,tm2);
        float al1 = ex2f(m1-m1n), al2 = ex2f(m2-m2n);
        float rs1=0.f, rs2=0.f;
        #pragma unroll
        for (int nt=0;nt<8;nt++){
            float p0 = ex2f(sacc[nt][0]*SL - m1n);
            float p1 = ex2f(sacc[nt][1]*SL - m1n);
            float p2 = ex2f(sacc[nt][2]*SL - m2n);
            float p3 = ex2f(sacc[nt][3]*SL - m2n);
            rs1 += p0+p1; rs2 += p2+p3;
            PS[(wm+g  )*SSTRIDE + 8*nt + pc0] = f2tf(p0);
            PS[(wm+g  )*SSTRIDE + 8*nt + pc1] = f2tf(p1);
            PS[(wm+g+8)*SSTRIDE + 8*nt + pc0] = f2tf(p2);
            PS[(wm+g+8)*SSTRIDE + 8*nt + pc1] = f2tf(p3);
        }
        rs1 += __shfl_xor_sync(~0u,rs1,1); rs1 += __shfl_xor_sync(~0u,rs1,2);
        rs2 += __shfl_xor_sync(~0u,rs2,1); rs2 += __shfl_xor_sync(~0u,rs2,2);
        l1 = l1*al1 + rs1; l2 = l2*al2 + rs2;
        m1 = m1n; m2 = m2n;
        #pragma unroll
        for (int dtl=0;dtl<8;dtl++){
            oacc[dtl][0]*=al1; oacc[dtl][1]*=al1;
            oacc[dtl][2]*=al2; oacc[dtl][3]*=al2;
        }
        __syncwarp();

        // --- O += P V ---
        #pragma unroll
        for (int k=0;k<8;k++){
            uint2 a02 = *(const uint2*)&PS[(wm+g  )*SSTRIDE + 8*k + 2*t];
            uint2 a13 = *(const uint2*)&PS[(wm+g+8)*SSTRIDE + 8*k + 2*t];
            #pragma unroll
            for (int dtl=0;dtl<8;dtl++){
                unsigned b0 = VS[(8*k  +t)*SSTRIDE + 8*dtl + g];
                unsigned b1 = VS[(8*k+4+t)*SSTRIDE + 8*dtl + g];
                mma8(oacc[dtl][0],oacc[dtl][1],oacc[dtl][2],oacc[dtl][3],
                     a02.x,a13.x,a02.y,a13.y, b0,b1);
            }
        }
        __syncthreads();
    }

    // --- write split partials ---
    int q1 = wm+g, q2 = wm+g+8;
    size_t pb = ((size_t)sp*NH + hd)*U_;
    if (t==0){
        if (q1<U_){ g_m[pb+q1]=m1; g_l[pb+q1]=l1; }
        if (q2<U_){ g_m[pb+q2]=m2; g_l[pb+q2]=l2; }
    }
    #pragma unroll
    for (int dtl=0;dtl<8;dtl++){
        int d0 = 8*dtl + 2*t;
        if (q1<U_) *(float2*)&g_opart[(pb+q1)*D_ + d0] = make_float2(oacc[dtl][0], oacc[dtl][1]);
        if (q2<U_) *(float2*)&g_opart[(pb+q2)*D_ + d0] = make_float2(oacc[dtl][2], oacc[dtl][3]);
    }
}

// ---------------- 5. combine splits + scatter into output ----------------
__global__ void combine_kernel(float* __restrict__ out){
    int q = blockIdx.x, hd = blockIdx.y, d = threadIdx.x;
    float mp[NSPLIT], lp[NSPLIT];
    float m = -1e30f;
    #pragma unroll
    for (int p=0;p<NSPLIT;p++){
        size_t pb = ((size_t)p*NH+hd)*U_ + q;
        mp[p] = g_m[pb]; lp[p] = g_l[pb];
        m = fmaxf(m, mp[p]);
    }
    float L=0.f, o=0.f;
    #pragma unroll
    for (int p=0;p<NSPLIT;p++){
        float w = ex2f(mp[p]-m);
        L += w*lp[p];
        o += w*g_opart[(((size_t)p*NH+hd)*U_+q)*D_ + d];
    }
    out[((size_t)hd*T_ + g_topidx[hd*U_+q])*D_ + d] = o / L;
}

// ---------------- launch ----------------
extern "C" void kernel_launch(void* const* d_in, const int* in_sizes, int n_in,
                              void* d_out, int out_size){
    (void)in_sizes; (void)n_in; (void)out_size;
    const float* Q = (const float*)d_in[0];
    const float* K = (const float*)d_in[1];
    const float* V = (const float*)d_in[2];
    float* out = (float*)d_out;

    const int smem_bytes = (2*KT + MROWS) * SSTRIDE * 4;  // 73984
    cudaFuncSetAttribute(attn_kernel, cudaFuncAttributeMaxDynamicSharedMemorySize, smem_bytes);

    qscore_kernel <<<NH*T_/8, 256>>>(Q);
    topk_kernel   <<<NH, 256>>>();
    vmean_kernel  <<<NH, 1024>>>(V);
    bcast_kernel  <<<8192, 256>>>((float4*)out);
    attn_kernel   <<<dim3(NSPLIT, NH), NWARPS*32, smem_bytes>>>(Q, K, V);
    combine_kernel<<<dim3(U_, NH), 64>>>(out);
}

// round 5
// speedup vs baseline: 1.2572x; 1.2572x over previous
#include <cuda_runtime.h>
#include <cstdint>

#define B_ 4
#define H_ 16
#define T_ 4096
#define D_ 64
#define U_ 134
#define NH (B_*H_)        // 64 heads
#define NSPLIT 2
#define KPS (T_/NSPLIT)   // 2048 keys per split
#define KT 64             // key tile
#define NTILES (KPS/KT)   // 32
#define MROWS 144         // 9 warps * 16 rows (134 padded)
#define NWARPS 9
#define SSTRIDE 68        // smem row stride in 32-bit words (bank-conflict pad)

// ---------------- device scratch (no allocations allowed) ----------------
__device__ __align__(16) float g_score[NH*T_];
__device__ int   g_topidx[NH*U_];
__device__ __align__(16) float g_vmean[NH*D_];
__device__ __align__(16) float g_m[NSPLIT*NH*U_];
__device__ __align__(16) float g_l[NSPLIT*NH*U_];
__device__ __align__(16) float g_opart[(size_t)NSPLIT*NH*U_*D_];

// ---------------- helpers ----------------
__device__ __forceinline__ float ex2f(float x){
    float y; asm("ex2.approx.ftz.f32 %0, %1;" : "=f"(y) : "f"(x)); return y;
}
__device__ __forceinline__ void mma8(float& d0,float& d1,float& d2,float& d3,
        unsigned a0,unsigned a1,unsigned a2,unsigned a3,
        unsigned b0,unsigned b1){
    asm volatile("mma.sync.aligned.m16n8k8.row.col.f32.tf32.tf32.f32 "
        "{%0,%1,%2,%3}, {%4,%5,%6,%7}, {%8,%9}, {%0,%1,%2,%3};"
        : "+f"(d0),"+f"(d1),"+f"(d2),"+f"(d3)
        : "r"(a0),"r"(a1),"r"(a2),"r"(a3),"r"(b0),"r"(b1));
}
// column permutation within each 8-group so that (t, t+4) are adjacent -> LDS.64 pairs
__device__ __forceinline__ int permd(int d){
    return (d & ~7) | ((d & 3) << 1) | ((d >> 2) & 1);
}
__device__ __forceinline__ void cpa4(unsigned dst, const float* src){
    asm volatile("cp.async.ca.shared.global [%0], [%1], 4;" :: "r"(dst), "l"(src));
}
__device__ __forceinline__ void cpa_commit(){
    asm volatile("cp.async.commit_group;");
}

// ---------------- 1. q_score = sum(Q*Q, -1) ----------------
__global__ void qscore_kernel(const float* __restrict__ Q){
    int row  = blockIdx.x*8 + (threadIdx.x>>5);
    int lane = threadIdx.x & 31;
    const float* q = Q + (size_t)row*D_;
    float a = q[lane], b = q[lane+32];
    float s = a*a + b*b;
    #pragma unroll
    for (int o=16;o;o>>=1) s += __shfl_xor_sync(~0u, s, o);
    if (!lane) g_score[row] = s;
}

// ---------------- 2. per-head top-134 (radix select on float bits; scores >= 0) ----------------
__global__ void topk_kernel(){
    int hd = blockIdx.x;
    const float* sc = g_score + hd*T_;
    __shared__ int hist[256];
    __shared__ unsigned s_prefix;
    __shared__ int s_rem, s_gt, s_eq, s_need;
    int tid = threadIdx.x;
    if (tid==0){ s_prefix=0u; s_rem=U_; }
    __syncthreads();
    for (int shift=24; shift>=0; shift-=8){
        hist[tid]=0;
        __syncthreads();
        unsigned pfx = s_prefix;
        for (int i=tid;i<T_;i+=256){
            unsigned b = __float_as_uint(sc[i]);
            bool match = (shift==24) || ((b>>(shift+8))==(pfx>>(shift+8)));
            if (match) atomicAdd(&hist[(b>>shift)&255],1);
        }
        __syncthreads();
        if (tid==0){
            int rem = s_rem, cum=0, d=255;
            for (; d>=0; --d){ cum += hist[d]; if (cum>=rem) break; }
            s_rem = rem - (cum - hist[d]);
            s_prefix = pfx | ((unsigned)d<<shift);
        }
        __syncthreads();
    }
    if (tid==0){ s_gt=0; s_eq=0; s_need=s_rem; }
    __syncthreads();
    unsigned Tb = s_prefix;
    int need = s_need;
    int base_eq = U_ - need;
    for (int i=tid;i<T_;i+=256){
        unsigned b = __float_as_uint(sc[i]);
        if (b > Tb){
            int p = atomicAdd(&s_gt,1);
            g_topidx[hd*U_+p] = i;
        } else if (b == Tb){
            int p = atomicAdd(&s_eq,1);
            if (p < need) g_topidx[hd*U_+base_eq+p] = i;
        }
    }
}

// ---------------- 3a. Vmean ----------------
__global__ void vmean_kernel(const float* __restrict__ V){
    int hd = blockIdx.x;
    int d  = threadIdx.x & 63, rg = threadIdx.x >> 6;   // block 1024 -> rg 0..15
    const float* v = V + (size_t)hd*T_*D_ + d;
    float acc=0.f;
    #pragma unroll 4
    for (int r=rg; r<T_; r+=16) acc += v[(size_t)r*D_];
    __shared__ float sm[1024];
    sm[threadIdx.x]=acc;
    __syncthreads();
    if (threadIdx.x < 64){
        float s=0.f;
        #pragma unroll
        for (int j=0;j<16;j++) s += sm[j*64 + d];
        g_vmean[hd*D_+d] = s * (1.0f/T_);
    }
}

// ---------------- 3b. broadcast Vmean to every output row ----------------
__global__ void bcast_kernel(float4* __restrict__ out){
    const float4* vm = (const float4*)g_vmean;
    unsigned idx = blockIdx.x*blockDim.x + threadIdx.x;
    #pragma unroll
    for (int it=0; it<2; ++it){
        unsigned j = idx + it*2097152u;
        unsigned head = j >> 16;     // 4096*16 float4 per head
        unsigned dq   = j & 15;
        out[j] = vm[head*16 + dq];
    }
}

// ---------------- 4. split-KV flash attention on selected queries (tf32 mma) ----------------
// Double-buffered cp.async staging. K stored [key][permd(d)]; V stored transposed
// [d][permd(key)] so both QK^T and PV B-fragments are single LDS.64 pairs.
__global__ void __launch_bounds__(NWARPS*32) attn_kernel(
        const float* __restrict__ Q, const float* __restrict__ K,
        const float* __restrict__ V){
    extern __shared__ unsigned smem[];
    // [stage0: K,VT][stage1: K,VT][PS]
    unsigned* PS = smem + 4*KT*SSTRIDE;   // MROWS x SSTRIDE (Q staging, then P)

    int sp = blockIdx.x, hd = blockIdx.y;
    int tid = threadIdx.x;
    int wid = tid>>5, lane = tid&31;
    int g = lane>>2, t = lane&3;
    int wm = wid*16;
    const float SL = 0.18033688011112042f;  // (1/sqrt(64)) * log2(e)

    unsigned smem_base = (unsigned)__cvta_generic_to_shared(smem);
    size_t kvbase = ((size_t)hd*T_ + (size_t)sp*KPS)*D_;
    const float* Kg0 = K + kvbase;
    const float* Vg0 = V + kvbase;

    // --- prologue: async-stage tiles 0 and 1 ---
    #pragma unroll 1
    for (int pre=0; pre<2; ++pre){
        unsigned kb = smem_base + pre*(2*KT*SSTRIDE*4);
        unsigned vb = kb + KT*SSTRIDE*4;
        const float* Kg = Kg0 + pre*KT*D_;
        const float* Vg = Vg0 + pre*KT*D_;
        for (int i=tid; i<KT*D_; i+=NWARPS*32){
            int r = i>>6, d = i&63;
            cpa4(kb + 4*(r*SSTRIDE + permd(d)), Kg+i);
            cpa4(vb + 4*(d*SSTRIDE + permd(r)), Vg+i);
        }
        cpa_commit();
    }

    // --- stage selected Q rows (padded to 144) into PS (raw f32 bits; mma truncates) ---
    const int* tix = g_topidx + hd*U_;
    {
        size_t qbase = (size_t)hd*T_*D_;
        for (int i=tid; i<MROWS*D_; i+=NWARPS*32){
            int r = i>>6, d = i&63;
            float v = 0.f;
            if (r < U_) v = Q[qbase + (size_t)tix[r]*D_ + d];
            PS[r*SSTRIDE + permd(d)] = __float_as_uint(v);
        }
    }
    __syncthreads();

    // --- Q A-fragments into registers (persist through key loop) ---
    unsigned qf[8][4];
    #pragma unroll
    for (int k=0;k<8;k++){
        uint2 lo = *(const uint2*)&PS[(wm+g  )*SSTRIDE + 8*k + 2*t];
        uint2 hi = *(const uint2*)&PS[(wm+g+8)*SSTRIDE + 8*k + 2*t];
        qf[k][0]=lo.x; qf[k][1]=hi.x; qf[k][2]=lo.y; qf[k][3]=hi.y;
    }

    float m1=-1e30f, m2=-1e30f, l1=0.f, l2=0.f;
    float oacc[8][4];
    #pragma unroll
    for (int dtl=0;dtl<8;dtl++){ oacc[dtl][0]=0.f; oacc[dtl][1]=0.f; oacc[dtl][2]=0.f; oacc[dtl][3]=0.f; }

    // P-store permuted column offsets (within an 8-group)
    int pc0 = (((2*t  )&3)<<1) | (((2*t  )>>2)&1);
    int pc1 = (((2*t+1)&3)<<1) | (((2*t+1)>>2)&1);

    #pragma unroll 1
    for (int ktile=0; ktile<NTILES; ++ktile){
        // wait for this tile's cp.async group (allow the next tile's to stay in flight)
        if (ktile+1 < NTILES) asm volatile("cp.async.wait_group 1;");
        else                  asm volatile("cp.async.wait_group 0;");
        __syncthreads();

        unsigned* KS = smem + (ktile&1)*(2*KT*SSTRIDE);
        unsigned* VS = KS + KT*SSTRIDE;     // transposed: [d][permd(key)]

        // --- S = Q K^T (16 x 64 per warp) ---
        float sacc[8][4];
        #pragma unroll
        for (int nt=0;nt<8;nt++){ sacc[nt][0]=0.f; sacc[nt][1]=0.f; sacc[nt][2]=0.f; sacc[nt][3]=0.f; }
        #pragma unroll
        for (int k=0;k<8;k++){
            #pragma unroll
            for (int nt=0;nt<8;nt++){
                uint2 b = *(const uint2*)&KS[(8*nt+g)*SSTRIDE + 8*k + 2*t];
                mma8(sacc[nt][0],sacc[nt][1],sacc[nt][2],sacc[nt][3],
                     qf[k][0],qf[k][1],qf[k][2],qf[k][3], b.x, b.y);
            }
        }

        // --- online softmax (base 2, scale folded) ---
        float tm1=-1e30f, tm2=-1e30f;
        #pragma unroll
        for (int nt=0;nt<8;nt++){
            tm1 = fmaxf(tm1, fmaxf(sacc[nt][0], sacc[nt][1]));
            tm2 = fmaxf(tm2, fmaxf(sacc[nt][2], sacc[nt][3]));
        }
        tm1 *= SL; tm2 *= SL;
        tm1 = fmaxf(tm1, __shfl_xor_sync(~0u,tm1,1)); tm1 = fmaxf(tm1, __shfl_xor_sync(~0u,tm1,2));
        tm2 = fmaxf(tm2, __shfl_xor_sync(~0u,tm2,1)); tm2 = fmaxf(tm2, __shfl_xor_sync(~0u,tm2,2));
        float m1n = fmaxf(m1,tm1), m2n = fmaxf(m2,tm2);
        float al1 = ex2f(m1-m1n), al2 = ex2f(m2-m2n);
        float rs1=0.f, rs2=0.f;
        #pragma unroll
        for (int nt=0;nt<8;nt++){
            float p0 = ex2f(sacc[nt][0]*SL - m1n);
            float p1 = ex2f(sacc[nt][1]*SL - m1n);
            float p2 = ex2f(sacc[nt][2]*SL - m2n);
            float p3 = ex2f(sacc[nt][3]*SL - m2n);
            rs1 += p0+p1; rs2 += p2+p3;
            PS[(wm+g  )*SSTRIDE + 8*nt + pc0] = __float_as_uint(p0);
            PS[(wm+g  )*SSTRIDE + 8*nt + pc1] = __float_as_uint(p1);
            PS[(wm+g+8)*SSTRIDE + 8*nt + pc0] = __float_as_uint(p2);
            PS[(wm+g+8)*SSTRIDE + 8*nt + pc1] = __float_as_uint(p3);
        }
        rs1 += __shfl_xor_sync(~0u,rs1,1); rs1 += __shfl_xor_sync(~0u,rs1,2);
        rs2 += __shfl_xor_sync(~0u,rs2,1); rs2 += __shfl_xor_sync(~0u,rs2,2);
        l1 = l1*al1 + rs1; l2 = l2*al2 + rs2;
        m1 = m1n; m2 = m2n;
        #pragma unroll
        for (int dtl=0;dtl<8;dtl++){
            oacc[dtl][0]*=al1; oacc[dtl][1]*=al1;
            oacc[dtl][2]*=al2; oacc[dtl][3]*=al2;
        }
        __syncwarp();

        // --- O += P V  (V^T layout: B-frag pairs are one LDS.64) ---
        #pragma unroll
        for (int k=0;k<8;k++){
            uint2 a02 = *(const uint2*)&PS[(wm+g  )*SSTRIDE + 8*k + 2*t];
            uint2 a13 = *(const uint2*)&PS[(wm+g+8)*SSTRIDE + 8*k + 2*t];
            #pragma unroll
            for (int dtl=0;dtl<8;dtl++){
                uint2 b = *(const uint2*)&VS[(8*dtl+g)*SSTRIDE + 8*k + 2*t];
                mma8(oacc[dtl][0],oacc[dtl][1],oacc[dtl][2],oacc[dtl][3],
                     a02.x,a13.x,a02.y,a13.y, b.x,b.y);
            }
        }
        __syncthreads();

        // --- async-stage tile ktile+2 into the buffer we just finished ---
        if (ktile+2 < NTILES){
            unsigned kb = smem_base + (ktile&1)*(2*KT*SSTRIDE*4);
            unsigned vb = kb + KT*SSTRIDE*4;
            const float* Kg = Kg0 + (ktile+2)*KT*D_;
            const float* Vg = Vg0 + (ktile+2)*KT*D_;
            for (int i=tid; i<KT*D_; i+=NWARPS*32){
                int r = i>>6, d = i&63;
                cpa4(kb + 4*(r*SSTRIDE + permd(d)), Kg+i);
                cpa4(vb + 4*(d*SSTRIDE + permd(r)), Vg+i);
            }
            cpa_commit();
        }
    }

    // --- write split partials ---
    int q1 = wm+g, q2 = wm+g+8;
    size_t pb = ((size_t)sp*NH + hd)*U_;
    if (t==0){
        if (q1<U_){ g_m[pb+q1]=m1; g_l[pb+q1]=l1; }
        if (q2<U_){ g_m[pb+q2]=m2; g_l[pb+q2]=l2; }
    }
    #pragma unroll
    for (int dtl=0;dtl<8;dtl++){
        int d0 = 8*dtl + 2*t;
        if (q1<U_) *(float2*)&g_opart[(pb+q1)*D_ + d0] = make_float2(oacc[dtl][0], oacc[dtl][1]);
        if (q2<U_) *(float2*)&g_opart[(pb+q2)*D_ + d0] = make_float2(oacc[dtl][2], oacc[dtl][3]);
    }
}

// ---------------- 5. combine splits + scatter into output ----------------
__global__ void combine_kernel(float* __restrict__ out){
    int q = blockIdx.x, hd = blockIdx.y, d = threadIdx.x;
    float mp[NSPLIT], lp[NSPLIT];
    float m = -1e30f;
    #pragma unroll
    for (int p=0;p<NSPLIT;p++){
        size_t pb = ((size_t)p*NH+hd)*U_ + q;
        mp[p] = g_m[pb]; lp[p] = g_l[pb];
        m = fmaxf(m, mp[p]);
    }
    float L=0.f, o=0.f;
    #pragma unroll
    for (int p=0;p<NSPLIT;p++){
        float w = ex2f(mp[p]-m);
        L += w*lp[p];
        o += w*g_opart[(((size_t)p*NH+hd)*U_+q)*D_ + d];
    }
    out[((size_t)hd*T_ + g_topidx[hd*U_+q])*D_ + d] = o / L;
}

// ---------------- launch ----------------
extern "C" void kernel_launch(void* const* d_in, const int* in_sizes, int n_in,
                              void* d_out, int out_size){
    (void)in_sizes; (void)n_in; (void)out_size;
    const float* Q = (const float*)d_in[0];
    const float* K = (const float*)d_in[1];
    const float* V = (const float*)d_in[2];
    float* out = (float*)d_out;

    const int smem_bytes = (4*KT + MROWS) * SSTRIDE * 4;  // 108800
    cudaFuncSetAttribute(attn_kernel, cudaFuncAttributeMaxDynamicSharedMemorySize, smem_bytes);

    qscore_kernel <<<NH*T_/8, 256>>>(Q);
    topk_kernel   <<<NH, 256>>>();
    vmean_kernel  <<<NH, 1024>>>(V);
    bcast_kernel  <<<8192, 256>>>((float4*)out);
    attn_kernel   <<<dim3(NSPLIT, NH), NWARPS*32, smem_bytes>>>(Q, K, V);
    combine_kernel<<<dim3(U_, NH), 64>>>(out);
}

// round 6
// speedup vs baseline: 1.2589x; 1.0013x over previous
#include <cuda_runtime.h>
#include <cstdint>

#define B_ 4
#define H_ 16
#define T_ 4096
#define D_ 64
#define U_ 134
#define NH (B_*H_)        // 64 heads
#define NSPLIT 2
#define KPS (T_/NSPLIT)   // 2048 keys per split
#define KT 64             // key tile
#define NTILES (KPS/KT)   // 32
#define MROWS 144         // 9 warps * 16 rows (134 padded)
#define NWARPS 9
#define SSTRIDE 68        // smem row stride in 32-bit words (bank-conflict pad)

// ---------------- device scratch (no allocations allowed) ----------------
__device__ __align__(16) float g_score[NH*T_];
__device__ int   g_topidx[NH*U_];
__device__ __align__(16) float g_vmean[NH*D_];
__device__ __align__(16) float g_m[NSPLIT*NH*U_];
__device__ __align__(16) float g_l[NSPLIT*NH*U_];
__device__ __align__(16) float g_opart[(size_t)NSPLIT*NH*U_*D_];

// ---------------- helpers ----------------
__device__ __forceinline__ float ex2f(float x){
    float y; asm("ex2.approx.ftz.f32 %0, %1;" : "=f"(y) : "f"(x)); return y;
}
__device__ __forceinline__ void mma8(float& d0,float& d1,float& d2,float& d3,
        unsigned a0,unsigned a1,unsigned a2,unsigned a3,
        unsigned b0,unsigned b1){
    asm volatile("mma.sync.aligned.m16n8k8.row.col.f32.tf32.tf32.f32 "
        "{%0,%1,%2,%3}, {%4,%5,%6,%7}, {%8,%9}, {%0,%1,%2,%3};"
        : "+f"(d0),"+f"(d1),"+f"(d2),"+f"(d3)
        : "r"(a0),"r"(a1),"r"(a2),"r"(a3),"r"(b0),"r"(b1));
}
// column permutation within each 8-group so that (t, t+4) are adjacent -> LDS.64 pairs
__device__ __forceinline__ int permd(int d){
    return (d & ~7) | ((d & 3) << 1) | ((d >> 2) & 1);
}
__device__ __forceinline__ void cpa4(unsigned dst, const float* src){
    asm volatile("cp.async.ca.shared.global [%0], [%1], 4;" :: "r"(dst), "l"(src));
}
__device__ __forceinline__ void cpa_commit(){
    asm volatile("cp.async.commit_group;");
}

// ---------------- 1. q_score = sum(Q*Q, -1) ----------------
__global__ void qscore_kernel(const float* __restrict__ Q){
    int row  = blockIdx.x*8 + (threadIdx.x>>5);
    int lane = threadIdx.x & 31;
    const float* q = Q + (size_t)row*D_;
    float a = q[lane], b = q[lane+32];
    float s = a*a + b*b;
    #pragma unroll
    for (int o=16;o;o>>=1) s += __shfl_xor_sync(~0u, s, o);
    if (!lane) g_score[row] = s;
}

// ---------------- 2. per-head top-134 (radix select on float bits; scores >= 0) ----------------
__global__ void topk_kernel(){
    int hd = blockIdx.x;
    const float* sc = g_score + hd*T_;
    __shared__ int hist[256];
    __shared__ unsigned s_prefix;
    __shared__ int s_rem, s_gt, s_eq, s_need;
    int tid = threadIdx.x;
    if (tid==0){ s_prefix=0u; s_rem=U_; }
    __syncthreads();
    for (int shift=24; shift>=0; shift-=8){
        hist[tid]=0;
        __syncthreads();
        unsigned pfx = s_prefix;
        for (int i=tid;i<T_;i+=256){
            unsigned b = __float_as_uint(sc[i]);
            bool match = (shift==24) || ((b>>(shift+8))==(pfx>>(shift+8)));
            if (match) atomicAdd(&hist[(b>>shift)&255],1);
        }
        __syncthreads();
        if (tid==0){
            int rem = s_rem, cum=0, d=255;
            for (; d>=0; --d){ cum += hist[d]; if (cum>=rem) break; }
            s_rem = rem - (cum - hist[d]);
            s_prefix = pfx | ((unsigned)d<<shift);
        }
        __syncthreads();
    }
    if (tid==0){ s_gt=0; s_eq=0; s_need=s_rem; }
    __syncthreads();
    unsigned Tb = s_prefix;
    int need = s_need;
    int base_eq = U_ - need;
    for (int i=tid;i<T_;i+=256){
        unsigned b = __float_as_uint(sc[i]);
        if (b > Tb){
            int p = atomicAdd(&s_gt,1);
            g_topidx[hd*U_+p] = i;
        } else if (b == Tb){
            int p = atomicAdd(&s_eq,1);
            if (p < need) g_topidx[hd*U_+base_eq+p] = i;
        }
    }
}

// ---------------- 3a. Vmean ----------------
__global__ void vmean_kernel(const float* __restrict__ V){
    int hd = blockIdx.x;
    int d  = threadIdx.x & 63, rg = threadIdx.x >> 6;   // block 1024 -> rg 0..15
    const float* v = V + (size_t)hd*T_*D_ + d;
    float acc=0.f;
    #pragma unroll 4
    for (int r=rg; r<T_; r+=16) acc += v[(size_t)r*D_];
    __shared__ float sm[1024];
    sm[threadIdx.x]=acc;
    __syncthreads();
    if (threadIdx.x < 64){
        float s=0.f;
        #pragma unroll
        for (int j=0;j<16;j++) s += sm[j*64 + d];
        g_vmean[hd*D_+d] = s * (1.0f/T_);
    }
}

// ---------------- 3b. broadcast Vmean to every output row ----------------
__global__ void bcast_kernel(float4* __restrict__ out){
    const float4* vm = (const float4*)g_vmean;
    unsigned idx = blockIdx.x*blockDim.x + threadIdx.x;
    #pragma unroll
    for (int it=0; it<2; ++it){
        unsigned j = idx + it*2097152u;
        unsigned head = j >> 16;     // 4096*16 float4 per head
        unsigned dq   = j & 15;
        out[j] = vm[head*16 + dq];
    }
}

// ---------------- 4. split-KV flash attention on selected queries (tf32 mma) ----------------
// Double-buffered cp.async staging. K stored [key][permd(d)]; V stored transposed
// [d][permd(key)] so both QK^T and PV B-fragments are single LDS.64 pairs.
__global__ void __launch_bounds__(NWARPS*32) attn_kernel(
        const float* __restrict__ Q, const float* __restrict__ K,
        const float* __restrict__ V){
    extern __shared__ unsigned smem[];
    // [stage0: K,VT][stage1: K,VT][PS]
    unsigned* PS = smem + 4*KT*SSTRIDE;   // MROWS x SSTRIDE (Q staging, then P)

    int sp = blockIdx.x, hd = blockIdx.y;
    int tid = threadIdx.x;
    int wid = tid>>5, lane = tid&31;
    int g = lane>>2, t = lane&3;
    int wm = wid*16;
    const float SL = 0.18033688011112042f;  // (1/sqrt(64)) * log2(e)

    unsigned smem_base = (unsigned)__cvta_generic_to_shared(smem);
    size_t kvbase = ((size_t)hd*T_ + (size_t)sp*KPS)*D_;
    const float* Kg0 = K + kvbase;
    const float* Vg0 = V + kvbase;

    // --- prologue: async-stage tiles 0 and 1 ---
    #pragma unroll 1
    for (int pre=0; pre<2; ++pre){
        unsigned kb = smem_base + pre*(2*KT*SSTRIDE*4);
        unsigned vb = kb + KT*SSTRIDE*4;
        const float* Kg = Kg0 + pre*KT*D_;
        const float* Vg = Vg0 + pre*KT*D_;
        for (int i=tid; i<KT*D_; i+=NWARPS*32){
            int r = i>>6, d = i&63;
            cpa4(kb + 4*(r*SSTRIDE + permd(d)), Kg+i);
            cpa4(vb + 4*(d*SSTRIDE + permd(r)), Vg+i);
        }
        cpa_commit();
    }

    // --- stage selected Q rows (padded to 144) into PS (raw f32 bits; mma truncates) ---
    const int* tix = g_topidx + hd*U_;
    {
        size_t qbase = (size_t)hd*T_*D_;
        for (int i=tid; i<MROWS*D_; i+=NWARPS*32){
            int r = i>>6, d = i&63;
            float v = 0.f;
            if (r < U_) v = Q[qbase + (size_t)tix[r]*D_ + d];
            PS[r*SSTRIDE + permd(d)] = __float_as_uint(v);
        }
    }
    __syncthreads();

    // --- Q A-fragments into registers (persist through key loop) ---
    unsigned qf[8][4];
    #pragma unroll
    for (int k=0;k<8;k++){
        uint2 lo = *(const uint2*)&PS[(wm+g  )*SSTRIDE + 8*k + 2*t];
        uint2 hi = *(const uint2*)&PS[(wm+g+8)*SSTRIDE + 8*k + 2*t];
        qf[k][0]=lo.x; qf[k][1]=hi.x; qf[k][2]=lo.y; qf[k][3]=hi.y;
    }

    float m1=-1e30f, m2=-1e30f, l1=0.f, l2=0.f;
    float oacc[8][4];
    #pragma unroll
    for (int dtl=0;dtl<8;dtl++){ oacc[dtl][0]=0.f; oacc[dtl][1]=0.f; oacc[dtl][2]=0.f; oacc[dtl][3]=0.f; }

    // P-store permuted column offsets (within an 8-group)
    int pc0 = (((2*t  )&3)<<1) | (((2*t  )>>2)&1);
    int pc1 = (((2*t+1)&3)<<1) | (((2*t+1)>>2)&1);

    #pragma unroll 1
    for (int ktile=0; ktile<NTILES; ++ktile){
        // wait for this tile's cp.async group (allow the next tile's to stay in flight)
        if (ktile+1 < NTILES) asm volatile("cp.async.wait_group 1;");
        else                  asm volatile("cp.async.wait_group 0;");
        __syncthreads();

        unsigned* KS = smem + (ktile&1)*(2*KT*SSTRIDE);
        unsigned* VS = KS + KT*SSTRIDE;     // transposed: [d][permd(key)]

        // --- S = Q K^T (16 x 64 per warp) ---
        float sacc[8][4];
        #pragma unroll
        for (int nt=0;nt<8;nt++){ sacc[nt][0]=0.f; sacc[nt][1]=0.f; sacc[nt][2]=0.f; sacc[nt][3]=0.f; }
        #pragma unroll
        for (int k=0;k<8;k++){
            #pragma unroll
            for (int nt=0;nt<8;nt++){
                uint2 b = *(const uint2*)&KS[(8*nt+g)*SSTRIDE + 8*k + 2*t];
                mma8(sacc[nt][0],sacc[nt][1],sacc[nt][2],sacc[nt][3],
                     qf[k][0],qf[k][1],qf[k][2],qf[k][3], b.x, b.y);
            }
        }

        // --- online softmax (base 2, scale folded) ---
        float tm1=-1e30f, tm2=-1e30f;
        #pragma unroll
        for (int nt=0;nt<8;nt++){
            tm1 = fmaxf(tm1, fmaxf(sacc[nt][0], sacc[nt][1]));
            tm2 = fmaxf(tm2, fmaxf(sacc[nt][2], sacc[nt][3]));
        }
        tm1 *= SL; tm2 *= SL;
        tm1 = fmaxf(tm1, __shfl_xor_sync(~0u,tm1,1)); tm1 = fmaxf(tm1, __shfl_xor_sync(~0u,tm1,2));
        tm2 = fmaxf(tm2, __shfl_xor_sync(~0u,tm2,1)); tm2 = fmaxf(tm2, __shfl_xor_sync(~0u,tm2,2));
        float m1n = fmaxf(m1,tm1), m2n = fmaxf(m2,tm2);
        float al1 = ex2f(m1-m1n), al2 = ex2f(m2-m2n);
        float rs1=0.f, rs2=0.f;
        #pragma unroll
        for (int nt=0;nt<8;nt++){
            float p0 = ex2f(sacc[nt][0]*SL - m1n);
            float p1 = ex2f(sacc[nt][1]*SL - m1n);
            float p2 = ex2f(sacc[nt][2]*SL - m2n);
            float p3 = ex2f(sacc[nt][3]*SL - m2n);
            rs1 += p0+p1; rs2 += p2+p3;
            PS[(wm+g  )*SSTRIDE + 8*nt + pc0] = __float_as_uint(p0);
            PS[(wm+g  )*SSTRIDE + 8*nt + pc1] = __float_as_uint(p1);
            PS[(wm+g+8)*SSTRIDE + 8*nt + pc0] = __float_as_uint(p2);
            PS[(wm+g+8)*SSTRIDE + 8*nt + pc1] = __float_as_uint(p3);
        }
        rs1 += __shfl_xor_sync(~0u,rs1,1); rs1 += __shfl_xor_sync(~0u,rs1,2);
        rs2 += __shfl_xor_sync(~0u,rs2,1); rs2 += __shfl_xor_sync(~0u,rs2,2);
        l1 = l1*al1 + rs1; l2 = l2*al2 + rs2;
        m1 = m1n; m2 = m2n;
        #pragma unroll
        for (int dtl=0;dtl<8;dtl++){
            oacc[dtl][0]*=al1; oacc[dtl][1]*=al1;
            oacc[dtl][2]*=al2; oacc[dtl][3]*=al2;
        }
        __syncwarp();

        // --- O += P V  (V^T layout: B-frag pairs are one LDS.64) ---
        #pragma unroll
        for (int k=0;k<8;k++){
            uint2 a02 = *(const uint2*)&PS[(wm+g  )*SSTRIDE + 8*k + 2*t];
            uint2 a13 = *(const uint2*)&PS[(wm+g+8)*SSTRIDE + 8*k + 2*t];
            #pragma unroll
            for (int dtl=0;dtl<8;dtl++){
                uint2 b = *(const uint2*)&VS[(8*dtl+g)*SSTRIDE + 8*k + 2*t];
                mma8(oacc[dtl][0],oacc[dtl][1],oacc[dtl][2],oacc[dtl][3],
                     a02.x,a13.x,a02.y,a13.y, b.x,b.y);
            }
        }
        __syncthreads();

        // --- async-stage tile ktile+2 into the buffer we just finished ---
        if (ktile+2 < NTILES){
            unsigned kb = smem_base + (ktile&1)*(2*KT*SSTRIDE*4);
            unsigned vb = kb + KT*SSTRIDE*4;
            const float* Kg = Kg0 + (ktile+2)*KT*D_;
            const float* Vg = Vg0 + (ktile+2)*KT*D_;
            for (int i=tid; i<KT*D_; i+=NWARPS*32){
                int r = i>>6, d = i&63;
                cpa4(kb + 4*(r*SSTRIDE + permd(d)), Kg+i);
                cpa4(vb + 4*(d*SSTRIDE + permd(r)), Vg+i);
            }
            cpa_commit();
        }
    }

    // --- write split partials ---
    int q1 = wm+g, q2 = wm+g+8;
    size_t pb = ((size_t)sp*NH + hd)*U_;
    if (t==0){
        if (q1<U_){ g_m[pb+q1]=m1; g_l[pb+q1]=l1; }
        if (q2<U_){ g_m[pb+q2]=m2; g_l[pb+q2]=l2; }
    }
    #pragma unroll
    for (int dtl=0;dtl<8;dtl++){
        int d0 = 8*dtl + 2*t;
        if (q1<U_) *(float2*)&g_opart[(pb+q1)*D_ + d0] = make_float2(oacc[dtl][0], oacc[dtl][1]);
        if (q2<U_) *(float2*)&g_opart[(pb+q2)*D_ + d0] = make_float2(oacc[dtl][2], oacc[dtl][3]);
    }
}

// ---------------- 5. combine splits + scatter into output ----------------
__global__ void combine_kernel(float* __restrict__ out){
    int q = blockIdx.x, hd = blockIdx.y, d = threadIdx.x;
    float mp[NSPLIT], lp[NSPLIT];
    float m = -1e30f;
    #pragma unroll
    for (int p=0;p<NSPLIT;p++){
        size_t pb = ((size_t)p*NH+hd)*U_ + q;
        mp[p] = g_m[pb]; lp[p] = g_l[pb];
        m = fmaxf(m, mp[p]);
    }
    float L=0.f, o=0.f;
    #pragma unroll
    for (int p=0;p<NSPLIT;p++){
        float w = ex2f(mp[p]-m);
        L += w*lp[p];
        o += w*g_opart[(((size_t)p*NH+hd)*U_+q)*D_ + d];
    }
    out[((size_t)hd*T_ + g_topidx[hd*U_+q])*D_ + d] = o / L;
}

// ---------------- launch ----------------
extern "C" void kernel_launch(void* const* d_in, const int* in_sizes, int n_in,
                              void* d_out, int out_size){
    (void)in_sizes; (void)n_in; (void)out_size;
    const float* Q = (const float*)d_in[0];
    const float* K = (const float*)d_in[1];
    const float* V = (const float*)d_in[2];
    float* out = (float*)d_out;

    const int smem_bytes = (4*KT + MROWS) * SSTRIDE * 4;  // 108800
    cudaFuncSetAttribute(attn_kernel, cudaFuncAttributeMaxDynamicSharedMemorySize, smem_bytes);

    qscore_kernel <<<NH*T_/8, 256>>>(Q);
    topk_kernel   <<<NH, 256>>>();
    vmean_kernel  <<<NH, 1024>>>(V);
    bcast_kernel  <<<8192, 256>>>((float4*)out);
    attn_kernel   <<<dim3(NSPLIT, NH), NWARPS*32, smem_bytes>>>(Q, K, V);
    combine_kernel<<<dim3(U_, NH), 64>>>(out);
}